// round 5
// baseline (speedup 1.0000x reference)
#include <cuda_runtime.h>
#include <cstdint>

// Problem constants
#define B_  16
#define H_  224
#define W_  224
#define C_  96
#define TW  32          // output pixels per block (one row segment)
#define NT  256         // threads per block
#define INW (TW + 2)    // 34 input cols incl. halo
#define DWP 97          // sDw pitch (odd -> conflict-free column reads)

// Shared-memory layout (in floats)
//   sW  : 96*96      = 9216
//   sIn : 3*34*96    = 9792   (ReLU'd input tile with halo, zero-padded)
//   sDw : 32*97      = 3104   (depthwise results, padded pitch)
//   sKw : 3*3*96     = 864    (depthwise weights)
//   sSc : 96                   (BN scale = gamma*rsqrt(var+eps))
//   sSh : 96                   (BN shift = beta - mean*scale + pw_bias*scale)
//   sDb : 96                   (depthwise bias)
#define OFF_W   0
#define OFF_IN  9216
#define OFF_DW  (9216 + 9792)
#define OFF_KW  (9216 + 9792 + 3104)
#define OFF_SC  (9216 + 9792 + 3104 + 864)
#define OFF_SH  (9216 + 9792 + 3104 + 864 + 96)
#define OFF_DB  (9216 + 9792 + 3104 + 864 + 192)
#define SMEM_FLOATS (9216 + 9792 + 3104 + 864 + 288)       // 23264
#define SMEM_BYTES  (SMEM_FLOATS * 4)                      // 93056

typedef unsigned long long ull;

__device__ __forceinline__ ull pack2(float lo, float hi) {
    ull r;
    asm("mov.b64 %0, {%1, %2};" : "=l"(r) : "f"(lo), "f"(hi));
    return r;
}
__device__ __forceinline__ void ffma2(ull& d, ull a, ull b) {
    // d = a * b + d  (packed f32x2 — 2x FFMA throughput, PTX-only pattern)
    asm("fma.rn.f32x2 %0, %1, %2, %0;" : "+l"(d) : "l"(a), "l"(b));
}
__device__ __forceinline__ ull ffma2_3(ull a, ull b, ull c) {
    ull d;
    asm("fma.rn.f32x2 %0, %1, %2, %3;" : "=l"(d) : "l"(a), "l"(b), "l"(c));
    return d;
}

__global__ void __launch_bounds__(NT, 2)
sepconv_kernel(const float* __restrict__ x,
               const float* __restrict__ dwk,    // (3,3,1,96)
               const float* __restrict__ dwb,    // (96)
               const float* __restrict__ pwk,    // (1,1,96,96) [ci][co]
               const float* __restrict__ pwb,    // (96)
               const float* __restrict__ gamma,
               const float* __restrict__ beta,
               const float* __restrict__ mmean,
               const float* __restrict__ mvar,
               float* __restrict__ out)
{
    extern __shared__ float sm[];
    float* sW  = sm + OFF_W;
    float* sIn = sm + OFF_IN;
    float* sDw = sm + OFF_DW;
    float* sKw = sm + OFF_KW;
    float* sSc = sm + OFF_SC;
    float* sSh = sm + OFF_SH;
    float* sDb = sm + OFF_DB;

    const int tid = threadIdx.x;
    const int w0  = blockIdx.x * TW;
    const int h   = blockIdx.y;
    const int b   = blockIdx.z;

    // ---- Phase 1: stage weights / BN params / input tile -------------------
    {   // pointwise weight matrix, vectorized
        const float4* src = (const float4*)pwk;
        float4* dst = (float4*)sW;
        #pragma unroll
        for (int i = tid; i < (C_ * C_) / 4; i += NT) dst[i] = src[i];
    }
    for (int i = tid; i < 9 * C_; i += NT) sKw[i] = dwk[i];
    if (tid < C_) {
        float inv = gamma[tid] * rsqrtf(mvar[tid] + 1e-3f);
        sSc[tid] = inv;
        sSh[tid] = beta[tid] - mmean[tid] * inv + pwb[tid] * inv;
        sDb[tid] = dwb[tid];
    }
    {   // input tile with halo: 3 rows x 34 cols x 96 ch, ReLU'd, zero-padded
        const int NQ = C_ / 4;               // 24 float4 per pixel
        for (int i = tid; i < 3 * INW * NQ; i += NT) {
            int pix = i / NQ;
            int q   = i - pix * NQ;
            int r   = pix / INW;
            int col = pix - r * INW;
            int gh  = h - 1 + r;
            int gw  = w0 - 1 + col;
            float4 v = make_float4(0.f, 0.f, 0.f, 0.f);
            if ((unsigned)gh < (unsigned)H_ && (unsigned)gw < (unsigned)W_) {
                v = *(const float4*)(x + (((size_t)b * H_ + gh) * W_ + gw) * C_ + q * 4);
                v.x = fmaxf(v.x, 0.f); v.y = fmaxf(v.y, 0.f);
                v.z = fmaxf(v.z, 0.f); v.w = fmaxf(v.w, 0.f);
            }
            *(float4*)(sIn + pix * C_ + q * 4) = v;
        }
    }
    __syncthreads();

    // ---- Phase 2: depthwise 3x3 -> sDw[p][c] -------------------------------
    #pragma unroll
    for (int i = 0; i < (TW * C_) / NT; i++) {         // 12 outputs / thread
        int idx = tid + i * NT;
        int p = idx / C_;
        int c = idx - p * C_;
        float acc = sDb[c];
        #pragma unroll
        for (int r = 0; r < 3; r++) {
            #pragma unroll
            for (int s = 0; s < 3; s++) {
                acc = fmaf(sIn[(r * INW + p + s) * C_ + c],
                           sKw[(r * 3 + s) * C_ + c], acc);
            }
        }
        sDw[p * DWP + c] = acc;
    }
    __syncthreads();

    // ---- Phase 3: pointwise 96x96 GEMM (f32x2) + BN + store ----------------
    // thread -> 2 pixels (pg*2, pg*2+1) x 6 output channels (cg*6 .. cg*6+5)
    const int pg = tid & 15;
    const int cg = tid >> 4;
    const int p0 = pg * 2;
    const int cb = cg * 6;

    ull acc0 = 0, acc1 = 0, acc2 = 0, acc3 = 0, acc4 = 0, acc5 = 0;

    const float* dw0 = sDw + p0 * DWP;
    const float* dw1 = sDw + (p0 + 1) * DWP;

    #pragma unroll 2
    for (int ci = 0; ci < C_; ci++) {
        float d0 = dw0[ci];
        float d1 = dw1[ci];
        ull dd0 = pack2(d0, d0);
        ull dd1 = pack2(d1, d1);
        const ull* w2 = (const ull*)(sW + ci * C_ + cb);
        ull w;
        w = w2[0]; ffma2(acc0, dd0, w); ffma2(acc3, dd1, w);
        w = w2[1]; ffma2(acc1, dd0, w); ffma2(acc4, dd1, w);
        w = w2[2]; ffma2(acc2, dd0, w); ffma2(acc5, dd1, w);
    }

    // BN (scale/shift) as one packed FMA, then 8B stores
    const ull s0 = *(const ull*)(sSc + cb);
    const ull s1 = *(const ull*)(sSc + cb + 2);
    const ull s2 = *(const ull*)(sSc + cb + 4);
    const ull t0 = *(const ull*)(sSh + cb);
    const ull t1 = *(const ull*)(sSh + cb + 2);
    const ull t2 = *(const ull*)(sSh + cb + 4);

    float* op0 = out + (((size_t)b * H_ + h) * W_ + (w0 + p0)) * C_ + cb;
    float* op1 = op0 + C_;

    *(ull*)(op0)     = ffma2_3(acc0, s0, t0);
    *(ull*)(op0 + 2) = ffma2_3(acc1, s1, t1);
    *(ull*)(op0 + 4) = ffma2_3(acc2, s2, t2);
    *(ull*)(op1)     = ffma2_3(acc3, s0, t0);
    *(ull*)(op1 + 2) = ffma2_3(acc4, s1, t1);
    *(ull*)(op1 + 4) = ffma2_3(acc5, s2, t2);
}

extern "C" void kernel_launch(void* const* d_in, const int* in_sizes, int n_in,
                              void* d_out, int out_size)
{
    (void)in_sizes; (void)n_in; (void)out_size;
    const float* x     = (const float*)d_in[0];
    const float* dwk   = (const float*)d_in[1];
    const float* dwb   = (const float*)d_in[2];
    const float* pwk   = (const float*)d_in[3];
    const float* pwb   = (const float*)d_in[4];
    const float* gamma = (const float*)d_in[5];
    const float* beta  = (const float*)d_in[6];
    const float* mmean = (const float*)d_in[7];
    const float* mvar  = (const float*)d_in[8];
    float* out = (float*)d_out;

    cudaFuncSetAttribute(sepconv_kernel,
                         cudaFuncAttributeMaxDynamicSharedMemorySize, SMEM_BYTES);

    dim3 grid(W_ / TW, H_, B_);
    sepconv_kernel<<<grid, NT, SMEM_BYTES>>>(
        x, dwk, dwb, pwk, pwb, gamma, beta, mmean, mvar, out);
}